// round 1
// baseline (speedup 1.0000x reference)
#include <cuda_runtime.h>

#define B_DIM 32
#define N_IN 1000000
#define N_OUT 500000

// 128 MB transposed scratch: xt[i][b], one 128B line per input column.
__device__ float g_xt[(size_t)N_IN * B_DIM];

// ---------------------------------------------------------------------------
// Kernel 1: transpose x(32, 1e6) -> xt(1e6, 32). Tiled 32x32 via smem.
// Block: 32x8 threads, each block handles a 32(cols) x 32(rows) tile.
// ---------------------------------------------------------------------------
__global__ void __launch_bounds__(256) transpose_kernel(const float* __restrict__ x) {
    __shared__ float tile[32][33];
    const int col0 = blockIdx.x * 32;
    const int tx = threadIdx.x;      // 0..31 : column within tile
    const int ty = threadIdx.y;      // 0..7

    // Coalesced read along N_IN (row b = ty+r)
    #pragma unroll
    for (int r = 0; r < 32; r += 8) {
        tile[ty + r][tx] = x[(size_t)(ty + r) * N_IN + (col0 + tx)];
    }
    __syncthreads();

    // Coalesced write: xt row (col0+ty+r) is 32 contiguous floats (lane = tx = b)
    #pragma unroll
    for (int r = 0; r < 32; r += 8) {
        g_xt[(size_t)(col0 + ty + r) * B_DIM + tx] = tile[tx][ty + r];
    }
}

// ---------------------------------------------------------------------------
// Kernel 2: gather-reduce. One warp per output column o.
//   lane = batch b: acc = sum_k w[o,k] * xt[idx[o,k]][b]   (3 coalesced 128B lines)
// Then block-local 32x32 smem transpose so out[b, o] stores are coalesced.
// Block: 32 warps -> 32 consecutive o per block.
// ---------------------------------------------------------------------------
__global__ void __launch_bounds__(1024) gather_kernel(const float* __restrict__ w,
                                                      const int*   __restrict__ idx,
                                                      float*       __restrict__ out) {
    __shared__ float s[32][33];
    const int warp = threadIdx.x >> 5;
    const int lane = threadIdx.x & 31;
    const int o = blockIdx.x * 32 + warp;

    // Uniform (broadcast) loads of the 3 indices + weights for this o
    const int base = o * 3;
    const int   i0 = __ldg(&idx[base + 0]);
    const int   i1 = __ldg(&idx[base + 1]);
    const int   i2 = __ldg(&idx[base + 2]);
    const float w0 = __ldg(&w[base + 0]);
    const float w1 = __ldg(&w[base + 1]);
    const float w2 = __ldg(&w[base + 2]);

    // Three fully-coalesced 128B line reads (lane = b)
    float acc = w0 * g_xt[(size_t)i0 * B_DIM + lane];
    acc = fmaf(w1, g_xt[(size_t)i1 * B_DIM + lane], acc);
    acc = fmaf(w2, g_xt[(size_t)i2 * B_DIM + lane], acc);

    // Transpose within block: s[b][o_local]
    s[lane][warp] = acc;
    __syncthreads();

    // Warp `warp` now writes batch row b = warp for 32 consecutive o (coalesced)
    out[(size_t)warp * N_OUT + (size_t)blockIdx.x * 32 + lane] = s[warp][lane];
}

// ---------------------------------------------------------------------------
extern "C" void kernel_launch(void* const* d_in, const int* in_sizes, int n_in,
                              void* d_out, int out_size) {
    const float* x   = (const float*)d_in[0];   // (32, 1e6) fp32
    const float* w   = (const float*)d_in[1];   // (5e5, 3)  fp32
    const int*   idx = (const int*)  d_in[2];   // (5e5, 3)  int32
    float*       out = (float*)d_out;           // (32, 5e5) fp32

    transpose_kernel<<<N_IN / 32, dim3(32, 8)>>>(x);
    gather_kernel<<<N_OUT / 32, 1024>>>(w, idx, out);
}

// round 2
// speedup vs baseline: 1.6434x; 1.6434x over previous
#include <cuda_runtime.h>

#define B_DIM 32
#define N_IN 1000000
#define N_OUT 500000
#define TILE_O 256
#define OPW 8   // outputs per warp (32 warps * 8 = TILE_O)

// 128 MB transposed scratch: xt[i][b], one 128B line per input column i.
__device__ float g_xt[(size_t)N_IN * B_DIM];

// ---------------------------------------------------------------------------
// Kernel 1: transpose x(32, 1e6) -> xt(1e6, 32).
// 32x32 tile per block, 256 threads. Scalar coalesced reads, conflict-free
// smem, one float4 STG per thread on the write side.
// ---------------------------------------------------------------------------
__global__ void __launch_bounds__(256) transpose_kernel(const float* __restrict__ x) {
    __shared__ float tile[32][33];
    const int col0 = blockIdx.x * 32;
    const int t  = threadIdx.x;
    const int tx = t & 31;    // column within tile
    const int ty = t >> 5;    // 0..7

    #pragma unroll
    for (int r = 0; r < 32; r += 8) {
        tile[ty + r][tx] = x[(size_t)(ty + r) * N_IN + (col0 + tx)];
    }
    __syncthreads();

    // Each thread emits one float4 of xt row (col0 + c), b-range [4q, 4q+4).
    // LDS banks: (4q+i)*33 + c  ->  (4(l%8)+i + l/8) mod 32 : conflict-free.
    const int c = t >> 3;     // 0..31 : xt row within tile (x column)
    const int q = t & 7;      // quad within the 32-float row
    float4 v;
    v.x = tile[4 * q + 0][c];
    v.y = tile[4 * q + 1][c];
    v.z = tile[4 * q + 2][c];
    v.w = tile[4 * q + 3][c];
    *reinterpret_cast<float4*>(&g_xt[(size_t)(col0 + c) * B_DIM + 4 * q]) = v;
}

// ---------------------------------------------------------------------------
// Kernel 2: gather-reduce, 256 outputs per block (1024 threads, 32 warps).
// Phase 0: stage idx/w for the whole tile into smem (coalesced).
// Phase 1: each warp computes 8 outputs -> 24 independent 128B gather loads.
// Phase 2: 32x256 smem transpose so out[b, o] stores are coalesced.
// ---------------------------------------------------------------------------
__global__ void __launch_bounds__(1024) gather_kernel(const float* __restrict__ w,
                                                      const int*   __restrict__ idx,
                                                      float*       __restrict__ out) {
    __shared__ int   s_idx[3 * TILE_O];
    __shared__ float s_w[3 * TILE_O];
    __shared__ float s_out[32][TILE_O + 1];

    const int tid  = threadIdx.x;
    const int warp = tid >> 5;
    const int lane = tid & 31;
    const int col0 = blockIdx.x * TILE_O;

    // Phase 0: coalesced staging of idx + w for this tile (768 each).
    if (tid < 3 * TILE_O) {
        const int gi = col0 * 3 + tid;
        const bool v = (gi < 3 * N_OUT);
        s_idx[tid] = v ? idx[gi] : 0;
        s_w[tid]   = v ? w[gi]   : 0.0f;
    }
    __syncthreads();

    // Phase 1: 8 outputs per warp; all 24 gather loads independent.
    #pragma unroll
    for (int j = 0; j < OPW; j++) {
        const int ol   = warp * OPW + j;      // local output within tile
        const int base = ol * 3;
        const int   i0 = s_idx[base + 0];
        const int   i1 = s_idx[base + 1];
        const int   i2 = s_idx[base + 2];
        const float w0 = s_w[base + 0];
        const float w1 = s_w[base + 1];
        const float w2 = s_w[base + 2];

        float a = w0 * g_xt[(size_t)i0 * B_DIM + lane];
        a = fmaf(w1, g_xt[(size_t)i1 * B_DIM + lane], a);
        a = fmaf(w2, g_xt[(size_t)i2 * B_DIM + lane], a);
        s_out[lane][ol] = a;
    }
    __syncthreads();

    // Phase 2: coalesced writes of the 32 x 256 tile.
    #pragma unroll
    for (int e = tid; e < 32 * TILE_O; e += 1024) {
        const int b  = e >> 8;            // batch row
        const int c  = e & (TILE_O - 1);  // column within tile
        const int oc = col0 + c;
        if (oc < N_OUT) out[(size_t)b * N_OUT + oc] = s_out[b][c];
    }
}

// ---------------------------------------------------------------------------
extern "C" void kernel_launch(void* const* d_in, const int* in_sizes, int n_in,
                              void* d_out, int out_size) {
    const float* x   = (const float*)d_in[0];   // (32, 1e6) fp32
    const float* w   = (const float*)d_in[1];   // (5e5, 3)  fp32
    const int*   idx = (const int*)  d_in[2];   // (5e5, 3)  int32
    float*       out = (float*)d_out;           // (32, 5e5) fp32

    transpose_kernel<<<N_IN / 32, 256>>>(x);
    gather_kernel<<<(N_OUT + TILE_O - 1) / TILE_O, 1024>>>(w, idx, out);
}

// round 3
// speedup vs baseline: 1.6802x; 1.0224x over previous
#include <cuda_runtime.h>

#define B_DIM 32
#define N_IN 1000000
#define N_OUT 500000

// 128 MB transposed scratch: xt[i][b], one 128B line per input column i.
__device__ float g_xt[(size_t)N_IN * B_DIM];

// ---------------------------------------------------------------------------
// Kernel 1: transpose x(32, 1e6) -> xt(1e6, 32).
// 32 rows x 128 cols tile per 1024-thread block. float4 reads, conflict-free
// smem (pad 129), float4 writes.
// ---------------------------------------------------------------------------
__global__ void __launch_bounds__(1024) transpose_kernel(const float* __restrict__ x) {
    __shared__ float tile[32][129];
    const int t    = threadIdx.x;
    const int col0 = blockIdx.x * 128;

    // Read phase: thread t reads one float4 of row (t>>5), cols col0+4*(t&31).
    {
        const int row = t >> 5;
        const int qc  = t & 31;
        const int c4  = col0 + 4 * qc;
        if (c4 < N_IN) {
            float4 v = *reinterpret_cast<const float4*>(&x[(size_t)row * N_IN + c4]);
            tile[row][4 * qc + 0] = v.x;
            tile[row][4 * qc + 1] = v.y;
            tile[row][4 * qc + 2] = v.z;
            tile[row][4 * qc + 3] = v.w;
        }
    }
    __syncthreads();

    // Write phase: thread t emits one float4 of xt row (col0 + c), b in [4q,4q+4).
    // LDS bank = ((4q+i)*129 + c) mod 32 = (4q + i + c) mod 32 : conflict-free.
    {
        const int c = t >> 3;   // 0..127 : x column within tile
        const int q = t & 7;    // quad of the 32-float xt row
        if (col0 + c < N_IN) {
            float4 v;
            v.x = tile[4 * q + 0][c];
            v.y = tile[4 * q + 1][c];
            v.z = tile[4 * q + 2][c];
            v.w = tile[4 * q + 3][c];
            *reinterpret_cast<float4*>(&g_xt[(size_t)(col0 + c) * B_DIM + 4 * q]) = v;
        }
    }
}

// ---------------------------------------------------------------------------
// Kernel 2: barrier-free gather-reduce. One warp per 8 consecutive outputs.
// lane<24 loads the warp's 24 idx/w (coalesced 96B), broadcast via shfl.
// 24 independent fully-coalesced 128B gather loads. lane = b writes its 8
// consecutive floats (one 32B sector) as two STG.128 — merged in L2.
// No shared memory, no __syncthreads: warps fully decoupled.
// ---------------------------------------------------------------------------
__global__ void __launch_bounds__(128) gather_kernel(const float* __restrict__ w,
                                                     const int*   __restrict__ idx,
                                                     float*       __restrict__ out) {
    const int warp = threadIdx.x >> 5;
    const int lane = threadIdx.x & 31;
    const int o0   = (blockIdx.x * 4 + warp) * 8;   // first of 8 outputs

    // Coalesced fetch of 24 idx + 24 w for this warp.
    int   iv = 0;
    float wv = 0.0f;
    if (lane < 24) {
        iv = __ldg(&idx[o0 * 3 + lane]);
        wv = __ldg(&w[o0 * 3 + lane]);
    }

    float acc[8];
    #pragma unroll
    for (int j = 0; j < 8; j++) {
        const int   i0 = __shfl_sync(0xffffffffu, iv, 3 * j + 0);
        const int   i1 = __shfl_sync(0xffffffffu, iv, 3 * j + 1);
        const int   i2 = __shfl_sync(0xffffffffu, iv, 3 * j + 2);
        const float w0 = __shfl_sync(0xffffffffu, wv, 3 * j + 0);
        const float w1 = __shfl_sync(0xffffffffu, wv, 3 * j + 1);
        const float w2 = __shfl_sync(0xffffffffu, wv, 3 * j + 2);

        float a = w0 * g_xt[(size_t)i0 * B_DIM + lane];
        a = fmaf(w1, g_xt[(size_t)i1 * B_DIM + lane], a);
        a = fmaf(w2, g_xt[(size_t)i2 * B_DIM + lane], a);
        acc[j] = a;
    }

    // lane = b: out[b][o0 .. o0+7] = 32 contiguous bytes, two float4 stores.
    float* p = out + (size_t)lane * N_OUT + o0;
    *reinterpret_cast<float4*>(p)     = make_float4(acc[0], acc[1], acc[2], acc[3]);
    *reinterpret_cast<float4*>(p + 4) = make_float4(acc[4], acc[5], acc[6], acc[7]);
}

// ---------------------------------------------------------------------------
extern "C" void kernel_launch(void* const* d_in, const int* in_sizes, int n_in,
                              void* d_out, int out_size) {
    const float* x   = (const float*)d_in[0];   // (32, 1e6) fp32
    const float* w   = (const float*)d_in[1];   // (5e5, 3)  fp32
    const int*   idx = (const int*)  d_in[2];   // (5e5, 3)  int32
    float*       out = (float*)d_out;           // (32, 5e5) fp32

    transpose_kernel<<<(N_IN + 127) / 128, 1024>>>(x);
    // 62500 warps total, 4 warps (128 threads) per block -> 15625 blocks exact.
    gather_kernel<<<N_OUT / 8 / 4, 128>>>(w, idx, out);
}

// round 4
// speedup vs baseline: 1.7127x; 1.0193x over previous
#include <cuda_runtime.h>

#define B_DIM 32
#define N_IN 1000000
#define N_OUT 500000

// 128 MB transposed scratch: xt[i][b], one 128B line per input column i.
__device__ float g_xt[(size_t)N_IN * B_DIM];

// ---------------------------------------------------------------------------
// Kernel 1: transpose x(32, 1e6) -> xt(1e6, 32).
// 32 rows x 128 cols tile per 256-thread block; each thread: 4 independent
// LDG.128, conflict-free smem (pad 129), 4 STG.128.
// ---------------------------------------------------------------------------
__global__ void __launch_bounds__(256) transpose_kernel(const float* __restrict__ x) {
    __shared__ float tile[32][129];
    const int t    = threadIdx.x;
    const int col0 = blockIdx.x * 128;

    // Read: thread t loads rows {t>>5, +8, +16, +24}, float4 at col 4*(t&31).
    {
        const int row = t >> 5;       // 0..7
        const int qc  = t & 31;
        const int c4  = col0 + 4 * qc;
        if (c4 < N_IN) {
            #pragma unroll
            for (int r = 0; r < 32; r += 8) {
                float4 v = *reinterpret_cast<const float4*>(
                    &x[(size_t)(row + r) * N_IN + c4]);
                tile[row + r][4 * qc + 0] = v.x;
                tile[row + r][4 * qc + 1] = v.y;
                tile[row + r][4 * qc + 2] = v.z;
                tile[row + r][4 * qc + 3] = v.w;
            }
        }
    }
    __syncthreads();

    // Write: thread t emits 4 float4s, xt rows {col0 + (t>>3) + 32m}, quad t&7.
    // LDS bank = ((4q+i)*129 + c) mod 32 = (4q+i+c) mod 32 : conflict-free.
    {
        const int c = t >> 3;   // 0..31
        const int q = t & 7;
        #pragma unroll
        for (int m = 0; m < 4; m++) {
            const int cc = c + 32 * m;
            if (col0 + cc < N_IN) {
                float4 v;
                v.x = tile[4 * q + 0][cc];
                v.y = tile[4 * q + 1][cc];
                v.z = tile[4 * q + 2][cc];
                v.w = tile[4 * q + 3][cc];
                *reinterpret_cast<float4*>(
                    &g_xt[(size_t)(col0 + cc) * B_DIM + 4 * q]) = v;
            }
        }
    }
}

// ---------------------------------------------------------------------------
// Kernel 2: gather-reduce. 256 threads (8 warps), 64 outputs per block.
// Each warp: 8 consecutive outputs, idx/w fetched coalesced (lane<24) and
// shfl-broadcast, 24 independent 128B gather LDGs (lane = b).
// Results staged in padded smem, then written with coalesced 128B stores.
// ---------------------------------------------------------------------------
__global__ void __launch_bounds__(256) gather_kernel(const float* __restrict__ w,
                                                     const int*   __restrict__ idx,
                                                     float*       __restrict__ out) {
    __shared__ float s_out[32][65];   // stride 65 = 1 mod 32 -> conflict-free cols

    const int tid  = threadIdx.x;
    const int warp = tid >> 5;
    const int lane = tid & 31;
    const int col0 = blockIdx.x * 64;            // first output of block
    const int o0   = col0 + warp * 8;            // first of this warp's 8 outputs

    if (o0 < N_OUT) {
        // Coalesced fetch of 24 idx + 24 w for this warp.
        int   iv = 0;
        float wv = 0.0f;
        if (lane < 24) {
            iv = __ldg(&idx[o0 * 3 + lane]);
            wv = __ldg(&w[o0 * 3 + lane]);
        }

        #pragma unroll
        for (int j = 0; j < 8; j++) {
            const int   i0 = __shfl_sync(0xffffffffu, iv, 3 * j + 0);
            const int   i1 = __shfl_sync(0xffffffffu, iv, 3 * j + 1);
            const int   i2 = __shfl_sync(0xffffffffu, iv, 3 * j + 2);
            const float w0 = __shfl_sync(0xffffffffu, wv, 3 * j + 0);
            const float w1 = __shfl_sync(0xffffffffu, wv, 3 * j + 1);
            const float w2 = __shfl_sync(0xffffffffu, wv, 3 * j + 2);

            float a = w0 * g_xt[(size_t)i0 * B_DIM + lane];
            a = fmaf(w1, g_xt[(size_t)i1 * B_DIM + lane], a);
            a = fmaf(w2, g_xt[(size_t)i2 * B_DIM + lane], a);
            s_out[lane][warp * 8 + j] = a;     // bank = (lane + c) % 32
        }
    }
    __syncthreads();

    // Coalesced writes: 2048 floats, 8 rounds. Warp covers 32 consecutive
    // floats of one batch row (128B wavefront). LDS bank = c % 32 : clean.
    #pragma unroll
    for (int k = 0; k < 8; k++) {
        const int e  = k * 256 + tid;
        const int b  = e >> 6;          // batch row
        const int c  = e & 63;          // column within tile
        const int oc = col0 + c;
        if (oc < N_OUT) out[(size_t)b * N_OUT + oc] = s_out[b][c];
    }
}

// ---------------------------------------------------------------------------
extern "C" void kernel_launch(void* const* d_in, const int* in_sizes, int n_in,
                              void* d_out, int out_size) {
    const float* x   = (const float*)d_in[0];   // (32, 1e6) fp32
    const float* w   = (const float*)d_in[1];   // (5e5, 3)  fp32
    const int*   idx = (const int*)  d_in[2];   // (5e5, 3)  int32
    float*       out = (float*)d_out;           // (32, 5e5) fp32

    transpose_kernel<<<(N_IN + 127) / 128, 256>>>(x);
    gather_kernel<<<(N_OUT + 63) / 64, 256>>>(w, idx, out);
}

// round 5
// speedup vs baseline: 2.3284x; 1.3595x over previous
#include <cuda_runtime.h>
#include <cuda_fp16.h>

#define B_DIM 32
#define N_IN 1000000
#define N_OUT 500000
#define TILE_O 128   // outputs per gather block (8 warps x 16)

// 64 MB transposed fp16 scratch: xt[i][b] -> 64B per input column i. Fits L2.
__device__ __half g_xt[(size_t)N_IN * B_DIM];

// ---------------------------------------------------------------------------
// Kernel 1: transpose+convert x(32,1e6) fp32 -> xt(1e6,32) fp16.
// 32 x 128 tile per 256-thread block. 4 independent LDG.128 per thread,
// conflict-free smem, 2 x STG.128 (8 halves each) per thread.
// ---------------------------------------------------------------------------
__global__ void __launch_bounds__(256) transpose_kernel(const float* __restrict__ x) {
    __shared__ float tile[32][129];
    const int t    = threadIdx.x;
    const int col0 = blockIdx.x * 128;

    // Read: thread t loads rows {t>>5 + 8r}, float4 at col 4*(t&31). MLP=4.
    {
        const int row = t >> 5;
        const int c4  = col0 + 4 * (t & 31);
        if (c4 < N_IN) {
            #pragma unroll
            for (int r = 0; r < 32; r += 8) {
                float4 v = *reinterpret_cast<const float4*>(
                    &x[(size_t)(row + r) * N_IN + c4]);
                tile[row + r][4 * (t & 31) + 0] = v.x;
                tile[row + r][4 * (t & 31) + 1] = v.y;
                tile[row + r][4 * (t & 31) + 2] = v.z;
                tile[row + r][4 * (t & 31) + 3] = v.w;
            }
        }
    }
    __syncthreads();

    // Write: 512 16B-chunks (xt row cc, b in [8q, 8q+8)); 2 per thread.
    // LDS bank = ((8q+i)*129 + cc) % 32 = (8q + i + cc) % 32 : conflict-free.
    #pragma unroll
    for (int m = 0; m < 2; m++) {
        const int e  = m * 256 + t;
        const int cc = e >> 2;     // 0..127 : row within tile (x column)
        const int q  = e & 3;      // 8-element b-chunk
        if (col0 + cc < N_IN) {
            __half2 h0 = __floats2half2_rn(tile[8 * q + 0][cc], tile[8 * q + 1][cc]);
            __half2 h1 = __floats2half2_rn(tile[8 * q + 2][cc], tile[8 * q + 3][cc]);
            __half2 h2 = __floats2half2_rn(tile[8 * q + 4][cc], tile[8 * q + 5][cc]);
            __half2 h3 = __floats2half2_rn(tile[8 * q + 6][cc], tile[8 * q + 7][cc]);
            uint4 u;
            u.x = *reinterpret_cast<unsigned*>(&h0);
            u.y = *reinterpret_cast<unsigned*>(&h1);
            u.z = *reinterpret_cast<unsigned*>(&h2);
            u.w = *reinterpret_cast<unsigned*>(&h3);
            *reinterpret_cast<uint4*>(
                &g_xt[(size_t)(col0 + cc) * B_DIM + 8 * q]) = u;
        }
    }
}

// ---------------------------------------------------------------------------
// Kernel 2: gather-reduce. 256 threads (8 warps), 128 outputs per block.
// Warp handles 16 outputs; each gather LDG serves TWO outputs (64B line each):
// lanes 0-15 -> output 2j (half2 = 2 b's per lane), lanes 16-31 -> output 2j+1.
// idx/w staged in smem (2-address broadcast LDS). Results staged b-major in
// padded smem, written as coalesced float4.
// ---------------------------------------------------------------------------
__global__ void __launch_bounds__(256) gather_kernel(const float* __restrict__ w,
                                                     const int*   __restrict__ idx,
                                                     float*       __restrict__ out) {
    __shared__ int   s_idx[3 * TILE_O];
    __shared__ float s_w[3 * TILE_O];
    __shared__ float s_out[32][133];   // pad 133: conflict-free STS pairs + LDS.128

    const int tid  = threadIdx.x;
    const int warp = tid >> 5;
    const int lane = tid & 31;
    const int h    = lane >> 4;   // which output of the pair
    const int r    = lane & 15;   // half2 slot: covers b = 2r, 2r+1
    const int col0 = blockIdx.x * TILE_O;

    // Stage idx + w for the tile (384 each), coalesced.
    #pragma unroll
    for (int m = 0; m < 2; m++) {
        const int e = m * 256 + tid;
        if (e < 3 * TILE_O) {
            const int gi = col0 * 3 + e;
            const bool v = (gi < 3 * N_OUT);
            s_idx[e] = v ? idx[gi] : 0;
            s_w[e]   = v ? w[gi]   : 0.0f;
        }
    }
    __syncthreads();

    const int o0 = col0 + warp * 16;
    if (o0 < N_OUT) {
        const __half2* xt2 = reinterpret_cast<const __half2*>(g_xt);
        #pragma unroll
        for (int j = 0; j < 8; j++) {
            const int eb = warp * 48 + (2 * j + h) * 3;
            float2 a = make_float2(0.0f, 0.0f);
            #pragma unroll
            for (int k = 0; k < 3; k++) {
                const int   i_ = s_idx[eb + k];     // 2 addrs/warp: broadcast
                const float w_ = s_w[eb + k];
                const float2 f = __half22float2(xt2[(size_t)i_ * 16 + r]);
                a.x = fmaf(w_, f.x, a.x);
                a.y = fmaf(w_, f.y, a.y);
            }
            const int ol = warp * 16 + 2 * j + h;
            // banks: (2r*133 + ol) -> 10r + h + c : all 32 distinct per instr
            s_out[2 * r + 0][ol] = a.x;
            s_out[2 * r + 1][ol] = a.y;
        }
    }
    __syncthreads();

    // Write 32 x 128 tile: 1024 float4, 4 per thread, coalesced 512B/warp.
    #pragma unroll
    for (int m = 0; m < 4; m++) {
        const int f4 = m * 256 + tid;
        const int b  = f4 >> 5;
        const int c4 = (f4 & 31) * 4;
        const int oc = col0 + c4;
        if (oc < N_OUT) {
            float4 v;
            v.x = s_out[b][c4 + 0];
            v.y = s_out[b][c4 + 1];
            v.z = s_out[b][c4 + 2];
            v.w = s_out[b][c4 + 3];
            *reinterpret_cast<float4*>(&out[(size_t)b * N_OUT + oc]) = v;
        }
    }
}

// ---------------------------------------------------------------------------
extern "C" void kernel_launch(void* const* d_in, const int* in_sizes, int n_in,
                              void* d_out, int out_size) {
    const float* x   = (const float*)d_in[0];   // (32, 1e6) fp32
    const float* w   = (const float*)d_in[1];   // (5e5, 3)  fp32
    const int*   idx = (const int*)  d_in[2];   // (5e5, 3)  int32
    float*       out = (float*)d_out;           // (32, 5e5) fp32

    transpose_kernel<<<(N_IN + 127) / 128, 256>>>(x);
    gather_kernel<<<(N_OUT + TILE_O - 1) / TILE_O, 256>>>(w, idx, out);
}

// round 8
// speedup vs baseline: 2.4644x; 1.0584x over previous
#include <cuda_runtime.h>
#include <cuda_fp16.h>

#define B_DIM 32
#define N_IN 1000000
#define N_OUT 500000
#define TILE_O 128
#define SOUT_STRIDE 132   // floats per b-row: = 4 mod 32, float4-aligned

// 64 MB transposed fp16 scratch: xt[i][b] -> one 64B line per input column i.
__device__ __half g_xt[(size_t)N_IN * B_DIM];

// ---------------------------------------------------------------------------
// Kernel 1: transpose+convert x(32,1e6) fp32 -> xt(1e6,32) fp16.
// 32 x 256 tile per 256-thread block. 8 independent LDG.128 per thread,
// conflict-free smem (pad 257), 4 x STG.128 (uint4 of 8 halves) per thread.
// ---------------------------------------------------------------------------
__global__ void __launch_bounds__(256) transpose_kernel(const float* __restrict__ x) {
    __shared__ float tile[32][257];
    const int t    = threadIdx.x;
    const int col0 = blockIdx.x * 256;

    // Read: 8 independent LDG.128 per thread (rows t>>5 + 8r, halves h).
    {
        const int row = t >> 5;
        const int qc  = 4 * (t & 31);
        #pragma unroll
        for (int h = 0; h < 2; h++) {
            const int c4 = col0 + qc + 128 * h;
            if (c4 < N_IN) {
                #pragma unroll
                for (int r = 0; r < 4; r++) {
                    float4 v = *reinterpret_cast<const float4*>(
                        &x[(size_t)(row + 8 * r) * N_IN + c4]);
                    tile[row + 8 * r][qc + 128 * h + 0] = v.x;
                    tile[row + 8 * r][qc + 128 * h + 1] = v.y;
                    tile[row + 8 * r][qc + 128 * h + 2] = v.z;
                    tile[row + 8 * r][qc + 128 * h + 3] = v.w;
                }
            }
        }
    }
    __syncthreads();

    // Write: 1024 16B-chunks (xt row cc, b in [8q,8q+8)); 4 per thread.
    // LDS bank = ((8q+i)*257 + cc) % 32 = (8q + i + cc) % 32 : conflict-free.
    #pragma unroll
    for (int m = 0; m < 4; m++) {
        const int e  = m * 256 + t;
        const int cc = e >> 2;     // 0..255 : row within tile (x column)
        const int q  = e & 3;      // 8-element b-chunk
        if (col0 + cc < N_IN) {
            __half2 h0 = __floats2half2_rn(tile[8 * q + 0][cc], tile[8 * q + 1][cc]);
            __half2 h1 = __floats2half2_rn(tile[8 * q + 2][cc], tile[8 * q + 3][cc]);
            __half2 h2 = __floats2half2_rn(tile[8 * q + 4][cc], tile[8 * q + 5][cc]);
            __half2 h3 = __floats2half2_rn(tile[8 * q + 6][cc], tile[8 * q + 7][cc]);
            uint4 u;
            u.x = *reinterpret_cast<unsigned*>(&h0);
            u.y = *reinterpret_cast<unsigned*>(&h1);
            u.z = *reinterpret_cast<unsigned*>(&h2);
            u.w = *reinterpret_cast<unsigned*>(&h3);
            *reinterpret_cast<uint4*>(
                &g_xt[(size_t)(col0 + cc) * B_DIM + 8 * q]) = u;
        }
    }
}

// ---------------------------------------------------------------------------
// Kernel 2: gather-reduce. 256 threads (8 warps), 128 outputs per block.
// One LDG.128 serves 8 outputs: lane (g = l>>2, s = l&3) reads 16B = 8 halves
// (b = 8s..8s+7) of output ol = base+g. (idx,w) packed as int2 -> LDS.64.
// Results staged b-major with XOR-swizzled columns (col ^ 8s): conflict-free
// STS.32 and conflict-free LDS.128 in the coalesced write phase.
// ---------------------------------------------------------------------------
__global__ void __launch_bounds__(256) gather_kernel(const float* __restrict__ w,
                                                     const int*   __restrict__ idx,
                                                     float*       __restrict__ out) {
    __shared__ int2  s_pair[3 * TILE_O];
    __shared__ float s_out[32 * SOUT_STRIDE];

    const int tid  = threadIdx.x;
    const int warp = tid >> 5;
    const int lane = tid & 31;
    const int g    = lane >> 2;   // output group (0..7)
    const int s    = lane & 3;    // 16B chunk: b = 8s..8s+7
    const int col0 = blockIdx.x * TILE_O;

    // Stage (idx, w) pairs for the tile, coalesced.
    #pragma unroll
    for (int m = 0; m < 2; m++) {
        const int e = m * 256 + tid;
        if (e < 3 * TILE_O) {
            const int gi = col0 * 3 + e;
            const bool v = (gi < 3 * N_OUT);
            s_pair[e] = make_int2(v ? idx[gi] : 0,
                                  v ? __float_as_int(w[gi]) : 0);
        }
    }
    __syncthreads();

    #pragma unroll
    for (int it = 0; it < 2; it++) {
        const int base = warp * 16 + it * 8;         // local output base
        if (col0 + base < N_OUT) {                   // N_OUT % 8 == 0 -> whole group
            const int ol = base + g;
            float acc[8] = {0, 0, 0, 0, 0, 0, 0, 0};
            #pragma unroll
            for (int k = 0; k < 3; k++) {
                const int2  p  = s_pair[ol * 3 + k];
                const float wk = __int_as_float(p.y);
                const uint4 v  = *reinterpret_cast<const uint4*>(
                    &g_xt[(size_t)p.x * B_DIM + 8 * s]);
                const float2 f0 = __half22float2(*reinterpret_cast<const __half2*>(&v.x));
                const float2 f1 = __half22float2(*reinterpret_cast<const __half2*>(&v.y));
                const float2 f2 = __half22float2(*reinterpret_cast<const __half2*>(&v.z));
                const float2 f3 = __half22float2(*reinterpret_cast<const __half2*>(&v.w));
                acc[0] = fmaf(wk, f0.x, acc[0]);
                acc[1] = fmaf(wk, f0.y, acc[1]);
                acc[2] = fmaf(wk, f1.x, acc[2]);
                acc[3] = fmaf(wk, f1.y, acc[3]);
                acc[4] = fmaf(wk, f2.x, acc[4]);
                acc[5] = fmaf(wk, f2.y, acc[5]);
                acc[6] = fmaf(wk, f3.x, acc[6]);
                acc[7] = fmaf(wk, f3.y, acc[7]);
            }
            // b-major staging, column XOR-swizzled by 8s (16B-granular).
            // bank = 4i + g + 8*(beta^s) : all 32 distinct per STS instr.
            const int colsw = ol ^ (8 * s);
            #pragma unroll
            for (int i = 0; i < 8; i++) {
                s_out[(8 * s + i) * SOUT_STRIDE + colsw] = acc[i];
            }
        }
    }
    __syncthreads();

    // Write 32 x 128 tile: 1024 float4; conflict-free LDS.128, coalesced STG.128.
    #pragma unroll
    for (int m = 0; m < 4; m++) {
        const int f4 = m * 256 + tid;
        const int b  = f4 >> 5;
        const int c4 = (f4 & 31) * 4;
        const int oc = col0 + c4;
        if (oc < N_OUT) {
            const int cst = c4 ^ (8 * (b >> 3));   // un-swizzle (4-aligned)
            float4 v = *reinterpret_cast<const float4*>(
                &s_out[b * SOUT_STRIDE + cst]);
            *reinterpret_cast<float4*>(&out[(size_t)b * N_OUT + oc]) = v;
        }
    }
}

// ---------------------------------------------------------------------------
extern "C" void kernel_launch(void* const* d_in, const int* in_sizes, int n_in,
                              void* d_out, int out_size) {
    const float* x   = (const float*)d_in[0];   // (32, 1e6) fp32
    const float* w   = (const float*)d_in[1];   // (5e5, 3)  fp32
    const int*   idx = (const int*)  d_in[2];   // (5e5, 3)  int32
    float*       out = (float*)d_out;           // (32, 5e5) fp32

    transpose_kernel<<<(N_IN + 255) / 256, 256>>>(x);
    gather_kernel<<<(N_OUT + TILE_O - 1) / TILE_O, 256>>>(w, idx, out);
}

// round 10
// speedup vs baseline: 2.6185x; 1.0625x over previous
#include <cuda_runtime.h>
#include <cuda_fp16.h>

#define B_DIM 32
#define N_IN 1000000
#define N_OUT 500000
#define TILE_O 256          // outputs per gather block (8 warps x 32)
#define SOUT_STRIDE 260     // floats per b-row: = 4 mod 32, float4-aligned

// 64 MB transposed fp16 scratch: xt[i][b] -> one 64B line per input column i.
// Goal: keep this L2-resident across both kernels (everything else streams).
__device__ __half g_xt[(size_t)N_IN * B_DIM];

// ---------------------------------------------------------------------------
// Kernel 1: transpose+convert x(32,1e6) fp32 -> xt(1e6,32) fp16.
// 32 x 128 tile per 256-thread block (R5 config). x reads use evict-first
// (__ldcs) so the streamed 128 MB doesn't evict xt from L2.
// ---------------------------------------------------------------------------
__global__ void __launch_bounds__(256) transpose_kernel(const float* __restrict__ x) {
    __shared__ float tile[32][129];
    const int t    = threadIdx.x;
    const int col0 = blockIdx.x * 128;

    // Read: thread t loads rows {t>>5 + 8r}, float4 at col 4*(t&31). MLP=4.
    {
        const int row = t >> 5;
        const int c4  = col0 + 4 * (t & 31);
        if (c4 < N_IN) {
            #pragma unroll
            for (int r = 0; r < 32; r += 8) {
                float4 v = __ldcs(reinterpret_cast<const float4*>(
                    &x[(size_t)(row + r) * N_IN + c4]));
                tile[row + r][4 * (t & 31) + 0] = v.x;
                tile[row + r][4 * (t & 31) + 1] = v.y;
                tile[row + r][4 * (t & 31) + 2] = v.z;
                tile[row + r][4 * (t & 31) + 3] = v.w;
            }
        }
    }
    __syncthreads();

    // Write: 512 16B-chunks (xt row cc, b in [8q,8q+8)); 2 per thread.
    // LDS bank = ((8q+i)*129 + cc) % 32 = (8q + i + cc) % 32 : conflict-free.
    #pragma unroll
    for (int m = 0; m < 2; m++) {
        const int e  = m * 256 + t;
        const int cc = e >> 2;     // 0..127 : row within tile (x column)
        const int q  = e & 3;      // 8-element b-chunk
        if (col0 + cc < N_IN) {
            __half2 h0 = __floats2half2_rn(tile[8 * q + 0][cc], tile[8 * q + 1][cc]);
            __half2 h1 = __floats2half2_rn(tile[8 * q + 2][cc], tile[8 * q + 3][cc]);
            __half2 h2 = __floats2half2_rn(tile[8 * q + 4][cc], tile[8 * q + 5][cc]);
            __half2 h3 = __floats2half2_rn(tile[8 * q + 6][cc], tile[8 * q + 7][cc]);
            uint4 u;
            u.x = *reinterpret_cast<unsigned*>(&h0);
            u.y = *reinterpret_cast<unsigned*>(&h1);
            u.z = *reinterpret_cast<unsigned*>(&h2);
            u.w = *reinterpret_cast<unsigned*>(&h3);
            *reinterpret_cast<uint4*>(
                &g_xt[(size_t)(col0 + cc) * B_DIM + 8 * q]) = u;   // keep in L2
        }
    }
}

// ---------------------------------------------------------------------------
// Kernel 2: gather-reduce. 256 threads (8 warps), 256 outputs per block.
// Per-warp idx/w staging (no block barrier). One LDG.128 serves 8 outputs:
// lane (g=l>>2, s=l&3) reads 16B = 8 halves (b=8s..8s+7) of output base+g.
// Single block barrier before the coalesced swizzled write-out (__stcs).
// ---------------------------------------------------------------------------
__global__ void __launch_bounds__(256) gather_kernel(const float* __restrict__ w,
                                                     const int*   __restrict__ idx,
                                                     float*       __restrict__ out) {
    __shared__ int2  s_pair[3 * TILE_O];            // (idx, w-bits) per entry
    __shared__ float s_out[32 * SOUT_STRIDE];

    const int tid  = threadIdx.x;
    const int warp = tid >> 5;
    const int lane = tid & 31;
    const int g    = lane >> 2;   // output group (0..7)
    const int s    = lane & 3;    // 16B chunk: b = 8s..8s+7
    const int col0 = blockIdx.x * TILE_O;
    const int o0   = col0 + warp * 32;              // warp's 32 outputs

    if (o0 < N_OUT) {
        // Per-warp staging: 96 (idx,w) pairs, coalesced, evict-first.
        const int gbase = o0 * 3;
        #pragma unroll
        for (int m = 0; m < 3; m++) {
            const int e = 32 * m + lane;
            s_pair[96 * warp + e] = make_int2(
                __ldcs(&idx[gbase + e]),
                __float_as_int(__ldcs(&w[gbase + e])));
        }
        __syncwarp();

        #pragma unroll
        for (int j = 0; j < 4; j++) {
            const int ol = warp * 32 + 8 * j + g;    // block-local output
            float acc[8] = {0, 0, 0, 0, 0, 0, 0, 0};
            #pragma unroll
            for (int k = 0; k < 3; k++) {
                const int2  p  = s_pair[ol * 3 + k];
                const float wk = __int_as_float(p.y);
                const uint4 v  = *reinterpret_cast<const uint4*>(
                    &g_xt[(size_t)p.x * B_DIM + 8 * s]);
                const float2 f0 = __half22float2(*reinterpret_cast<const __half2*>(&v.x));
                const float2 f1 = __half22float2(*reinterpret_cast<const __half2*>(&v.y));
                const float2 f2 = __half22float2(*reinterpret_cast<const __half2*>(&v.z));
                const float2 f3 = __half22float2(*reinterpret_cast<const __half2*>(&v.w));
                acc[0] = fmaf(wk, f0.x, acc[0]);
                acc[1] = fmaf(wk, f0.y, acc[1]);
                acc[2] = fmaf(wk, f1.x, acc[2]);
                acc[3] = fmaf(wk, f1.y, acc[3]);
                acc[4] = fmaf(wk, f2.x, acc[4]);
                acc[5] = fmaf(wk, f2.y, acc[5]);
                acc[6] = fmaf(wk, f3.x, acc[6]);
                acc[7] = fmaf(wk, f3.y, acc[7]);
            }
            // b-major staging, col XOR-swizzled by 8s (16B granular).
            // bank = 4i + g + 8*(j^s) : all 32 lanes distinct per STS instr.
            const int colsw = ol ^ (8 * s);
            #pragma unroll
            for (int i = 0; i < 8; i++) {
                s_out[(8 * s + i) * SOUT_STRIDE + colsw] = acc[i];
            }
        }
    }
    __syncthreads();

    // Write 32 x 256 tile: 2048 float4, 8 per thread; conflict-free LDS.128,
    // coalesced 512B STG.128 per warp, streamed past L2 (__stcs).
    #pragma unroll
    for (int m = 0; m < 8; m++) {
        const int f4 = m * 256 + tid;
        const int b  = f4 >> 6;           // batch row
        const int c4 = (f4 & 63) * 4;     // column within tile
        const int oc = col0 + c4;
        if (oc < N_OUT) {
            const int cst = c4 ^ (8 * (b >> 3));   // un-swizzle (16B aligned)
            float4 v = *reinterpret_cast<const float4*>(
                &s_out[b * SOUT_STRIDE + cst]);
            __stcs(reinterpret_cast<float4*>(&out[(size_t)b * N_OUT + oc]), v);
        }
    }
}

// ---------------------------------------------------------------------------
extern "C" void kernel_launch(void* const* d_in, const int* in_sizes, int n_in,
                              void* d_out, int out_size) {
    const float* x   = (const float*)d_in[0];   // (32, 1e6) fp32
    const float* w   = (const float*)d_in[1];   // (5e5, 3)  fp32
    const int*   idx = (const int*)  d_in[2];   // (5e5, 3)  int32
    float*       out = (float*)d_out;           // (32, 5e5) fp32

    transpose_kernel<<<(N_IN + 127) / 128, 256>>>(x);
    gather_kernel<<<(N_OUT + TILE_O - 1) / TILE_O, 256>>>(w, idx, out);
}

// round 11
// speedup vs baseline: 2.9074x; 1.1103x over previous
#include <cuda_runtime.h>
#include <cuda_fp16.h>

#define B_DIM 32
#define N_IN 1000000
#define N_OUT 500000
#define TILE_O 128
#define SOUT_STRIDE 132   // floats per b-row: = 4 mod 32, float4-aligned

// 64 MB transposed fp16 scratch: xt[i][b] -> one 64B line per input column i.
// Kept L2-resident: all other streams use evict-first hints.
__device__ __half g_xt[(size_t)N_IN * B_DIM];

// ---------------------------------------------------------------------------
// Kernel 1: transpose+convert x(32,1e6) fp32 -> xt(1e6,32) fp16.
// 32 x 128 tile per 256-thread block. __ldcs streamed reads (protect L2),
// conflict-free smem, STG.128 xt writes that stay in L2.
// ---------------------------------------------------------------------------
__global__ void __launch_bounds__(256) transpose_kernel(const float* __restrict__ x) {
    __shared__ float tile[32][129];
    const int t    = threadIdx.x;
    const int col0 = blockIdx.x * 128;

    // Read: thread t loads rows {t>>5 + 8r}, float4 at col 4*(t&31). MLP=4.
    {
        const int row = t >> 5;
        const int c4  = col0 + 4 * (t & 31);
        if (c4 < N_IN) {
            #pragma unroll
            for (int r = 0; r < 32; r += 8) {
                float4 v = __ldcs(reinterpret_cast<const float4*>(
                    &x[(size_t)(row + r) * N_IN + c4]));
                tile[row + r][4 * (t & 31) + 0] = v.x;
                tile[row + r][4 * (t & 31) + 1] = v.y;
                tile[row + r][4 * (t & 31) + 2] = v.z;
                tile[row + r][4 * (t & 31) + 3] = v.w;
            }
        }
    }
    __syncthreads();

    // Write: 512 16B-chunks (xt row cc, b in [8q,8q+8)); 2 per thread.
    // LDS bank = ((8q+i)*129 + cc) % 32 = (8q + i + cc) % 32 : conflict-free.
    #pragma unroll
    for (int m = 0; m < 2; m++) {
        const int e  = m * 256 + t;
        const int cc = e >> 2;     // 0..127 : row within tile (x column)
        const int q  = e & 3;      // 8-element b-chunk
        if (col0 + cc < N_IN) {
            __half2 h0 = __floats2half2_rn(tile[8 * q + 0][cc], tile[8 * q + 1][cc]);
            __half2 h1 = __floats2half2_rn(tile[8 * q + 2][cc], tile[8 * q + 3][cc]);
            __half2 h2 = __floats2half2_rn(tile[8 * q + 4][cc], tile[8 * q + 5][cc]);
            __half2 h3 = __floats2half2_rn(tile[8 * q + 6][cc], tile[8 * q + 7][cc]);
            uint4 u;
            u.x = *reinterpret_cast<unsigned*>(&h0);
            u.y = *reinterpret_cast<unsigned*>(&h1);
            u.z = *reinterpret_cast<unsigned*>(&h2);
            u.w = *reinterpret_cast<unsigned*>(&h3);
            *reinterpret_cast<uint4*>(
                &g_xt[(size_t)(col0 + cc) * B_DIM + 8 * q]) = u;   // keep in L2
        }
    }
}

// ---------------------------------------------------------------------------
// Kernel 2: gather-reduce (R8 structure). 256 threads (8 warps), 128 outputs
// per block. One LDG.128 serves 8 outputs: lane (g=l>>2, s=l&3) reads 16B =
// 8 halves (b=8s..8s+7) of output base+g. (idx,w) packed int2 in smem.
// Results staged b-major with XOR-swizzled columns; coalesced __stcs writes.
// ---------------------------------------------------------------------------
__global__ void __launch_bounds__(256) gather_kernel(const float* __restrict__ w,
                                                     const int*   __restrict__ idx,
                                                     float*       __restrict__ out) {
    __shared__ int2  s_pair[3 * TILE_O];
    __shared__ float s_out[32 * SOUT_STRIDE];

    const int tid  = threadIdx.x;
    const int warp = tid >> 5;
    const int lane = tid & 31;
    const int g    = lane >> 2;   // output group (0..7)
    const int s    = lane & 3;    // 16B chunk: b = 8s..8s+7
    const int col0 = blockIdx.x * TILE_O;

    // Stage (idx, w) pairs for the tile, coalesced + evict-first.
    #pragma unroll
    for (int m = 0; m < 2; m++) {
        const int e = m * 256 + tid;
        if (e < 3 * TILE_O) {
            const int gi = col0 * 3 + e;
            const bool v = (gi < 3 * N_OUT);
            s_pair[e] = make_int2(v ? __ldcs(&idx[gi]) : 0,
                                  v ? __float_as_int(__ldcs(&w[gi])) : 0);
        }
    }
    __syncthreads();

    #pragma unroll
    for (int it = 0; it < 2; it++) {
        const int base = warp * 16 + it * 8;         // local output base
        if (col0 + base < N_OUT) {                   // N_OUT % 8 == 0
            const int ol = base + g;
            float acc[8] = {0, 0, 0, 0, 0, 0, 0, 0};
            #pragma unroll
            for (int k = 0; k < 3; k++) {
                const int2  p  = s_pair[ol * 3 + k];
                const float wk = __int_as_float(p.y);
                const uint4 v  = *reinterpret_cast<const uint4*>(
                    &g_xt[(size_t)p.x * B_DIM + 8 * s]);
                const float2 f0 = __half22float2(*reinterpret_cast<const __half2*>(&v.x));
                const float2 f1 = __half22float2(*reinterpret_cast<const __half2*>(&v.y));
                const float2 f2 = __half22float2(*reinterpret_cast<const __half2*>(&v.z));
                const float2 f3 = __half22float2(*reinterpret_cast<const __half2*>(&v.w));
                acc[0] = fmaf(wk, f0.x, acc[0]);
                acc[1] = fmaf(wk, f0.y, acc[1]);
                acc[2] = fmaf(wk, f1.x, acc[2]);
                acc[3] = fmaf(wk, f1.y, acc[3]);
                acc[4] = fmaf(wk, f2.x, acc[4]);
                acc[5] = fmaf(wk, f2.y, acc[5]);
                acc[6] = fmaf(wk, f3.x, acc[6]);
                acc[7] = fmaf(wk, f3.y, acc[7]);
            }
            // b-major staging, column XOR-swizzled by 8s (16B-granular).
            const int colsw = ol ^ (8 * s);
            #pragma unroll
            for (int i = 0; i < 8; i++) {
                s_out[(8 * s + i) * SOUT_STRIDE + colsw] = acc[i];
            }
        }
    }
    __syncthreads();

    // Write 32 x 128 tile: 1024 float4; conflict-free LDS.128, coalesced
    // STG.128 streamed past L2 (__stcs).
    #pragma unroll
    for (int m = 0; m < 4; m++) {
        const int f4 = m * 256 + tid;
        const int b  = f4 >> 5;
        const int c4 = (f4 & 31) * 4;
        const int oc = col0 + c4;
        if (oc < N_OUT) {
            const int cst = c4 ^ (8 * (b >> 3));   // un-swizzle (16B aligned)
            float4 v = *reinterpret_cast<const float4*>(
                &s_out[b * SOUT_STRIDE + cst]);
            __stcs(reinterpret_cast<float4*>(&out[(size_t)b * N_OUT + oc]), v);
        }
    }
}

// ---------------------------------------------------------------------------
extern "C" void kernel_launch(void* const* d_in, const int* in_sizes, int n_in,
                              void* d_out, int out_size) {
    const float* x   = (const float*)d_in[0];   // (32, 1e6) fp32
    const float* w   = (const float*)d_in[1];   // (5e5, 3)  fp32
    const int*   idx = (const int*)  d_in[2];   // (5e5, 3)  int32
    float*       out = (float*)d_out;           // (32, 5e5) fp32

    transpose_kernel<<<(N_IN + 127) / 128, 256>>>(x);
    gather_kernel<<<(N_OUT + TILE_O - 1) / TILE_O, 256>>>(w, idx, out);
}